// round 2
// baseline (speedup 1.0000x reference)
#include <cuda_runtime.h>
#include <math.h>

// Problem shape (fixed by the dataset)
#define B_  4
#define S_  2048
#define D_  1024
#define M_TOT (B_ * S_)   // 8192

// Scratch (allocation-free rule: __device__ globals)
__device__ float g_q[(size_t)M_TOT * D_];
__device__ float g_k[(size_t)M_TOT * D_];
__device__ float g_v[(size_t)M_TOT * D_];
__device__ float g_s[(size_t)B_ * S_ * S_];   // 64 MB scores / softmax in place

#define BM 128
#define BN 128
#define BK 8
#define TM 8
#define TN 8

// C[M,N] = A[M,K] * B[K,N], all row-major. Batched via grid.z with element strides.
__global__ __launch_bounds__(256) void sgemm_nn(
    const float* __restrict__ A, const float* __restrict__ Bm, float* __restrict__ C,
    int M, int N, int K, long sA, long sB, long sC)
{
    A  += (long)blockIdx.z * sA;
    Bm += (long)blockIdx.z * sB;
    C  += (long)blockIdx.z * sC;

    __shared__ float As[BK][BM];
    __shared__ float Bs[BK][BN];

    const int tid = threadIdx.x;
    const int bx = blockIdx.x * BN;
    const int by = blockIdx.y * BM;

    const int arow = tid >> 1;          // 0..127
    const int acol = (tid & 1) * 4;     // 0 or 4
    const int brow = tid >> 5;          // 0..7
    const int bcol = (tid & 31) * 4;    // 0..124

    const int tx = (tid & 15) * TN;
    const int ty = (tid >> 4) * TM;

    float acc[TM][TN] = {};

    // Prologue: load first K-slice
    float4 av = *(const float4*)(A + (long)(by + arow) * K + acol);
    float4 bv = *(const float4*)(Bm + (long)brow * N + (bx + bcol));

    for (int k0 = 0; k0 < K; k0 += BK) {
        // Stage current slice into shared
        As[acol + 0][arow] = av.x;
        As[acol + 1][arow] = av.y;
        As[acol + 2][arow] = av.z;
        As[acol + 3][arow] = av.w;
        *(float4*)&Bs[brow][bcol] = bv;
        __syncthreads();

        // Prefetch next slice (overlaps with FMA loop below)
        if (k0 + BK < K) {
            av = *(const float4*)(A + (long)(by + arow) * K + (k0 + BK + acol));
            bv = *(const float4*)(Bm + (long)(k0 + BK + brow) * N + (bx + bcol));
        }

        #pragma unroll
        for (int k = 0; k < BK; k++) {
            float a[TM], b[TN];
            #pragma unroll
            for (int i = 0; i < TM; i++) a[i] = As[k][ty + i];
            #pragma unroll
            for (int j = 0; j < TN; j++) b[j] = Bs[k][tx + j];
            #pragma unroll
            for (int i = 0; i < TM; i++)
                #pragma unroll
                for (int j = 0; j < TN; j++)
                    acc[i][j] = fmaf(a[i], b[j], acc[i][j]);
        }
        __syncthreads();
    }

    #pragma unroll
    for (int i = 0; i < TM; i++) {
        #pragma unroll
        for (int j = 0; j < TN; j += 4) {
            float4 o = make_float4(acc[i][j], acc[i][j+1], acc[i][j+2], acc[i][j+3]);
            *(float4*)(C + (long)(by + ty + i) * N + (bx + tx + j)) = o;
        }
    }
}

// C[M,N] = A[M,K] * B[N,K]^T, A and B row-major. Batched via grid.z.
__global__ __launch_bounds__(256) void sgemm_nt(
    const float* __restrict__ A, const float* __restrict__ Bm, float* __restrict__ C,
    int M, int N, int K, long sA, long sB, long sC)
{
    A  += (long)blockIdx.z * sA;
    Bm += (long)blockIdx.z * sB;
    C  += (long)blockIdx.z * sC;

    __shared__ float As[BK][BM];
    __shared__ float Bs[BK][BN];

    const int tid = threadIdx.x;
    const int bx = blockIdx.x * BN;
    const int by = blockIdx.y * BM;

    const int row = tid >> 1;           // 0..127  (shared by A and B tile loads)
    const int col = (tid & 1) * 4;      // 0 or 4

    const int tx = (tid & 15) * TN;
    const int ty = (tid >> 4) * TM;

    float acc[TM][TN] = {};

    float4 av = *(const float4*)(A + (long)(by + row) * K + col);
    float4 bv = *(const float4*)(Bm + (long)(bx + row) * K + col);

    for (int k0 = 0; k0 < K; k0 += BK) {
        As[col + 0][row] = av.x;
        As[col + 1][row] = av.y;
        As[col + 2][row] = av.z;
        As[col + 3][row] = av.w;
        Bs[col + 0][row] = bv.x;
        Bs[col + 1][row] = bv.y;
        Bs[col + 2][row] = bv.z;
        Bs[col + 3][row] = bv.w;
        __syncthreads();

        if (k0 + BK < K) {
            av = *(const float4*)(A + (long)(by + row) * K + (k0 + BK + col));
            bv = *(const float4*)(Bm + (long)(bx + row) * K + (k0 + BK + col));
        }

        #pragma unroll
        for (int k = 0; k < BK; k++) {
            float a[TM], b[TN];
            #pragma unroll
            for (int i = 0; i < TM; i++) a[i] = As[k][ty + i];
            #pragma unroll
            for (int j = 0; j < TN; j++) b[j] = Bs[k][tx + j];
            #pragma unroll
            for (int i = 0; i < TM; i++)
                #pragma unroll
                for (int j = 0; j < TN; j++)
                    acc[i][j] = fmaf(a[i], b[j], acc[i][j]);
        }
        __syncthreads();
    }

    #pragma unroll
    for (int i = 0; i < TM; i++) {
        #pragma unroll
        for (int j = 0; j < TN; j += 4) {
            float4 o = make_float4(acc[i][j], acc[i][j+1], acc[i][j+2], acc[i][j+3]);
            *(float4*)(C + (long)(by + ty + i) * N + (bx + tx + j)) = o;
        }
    }
}

// In-place row softmax: one block (256 threads) per row of `ncols` (=2048) floats.
__global__ __launch_bounds__(256) void softmax_rows(float* __restrict__ Sp, int ncols)
{
    float* p = Sp + (long)blockIdx.x * ncols;
    const int tid = threadIdx.x;
    const int PER = S_ / 256;  // 8

    float vals[PER];
    float lmax = -INFINITY;
    #pragma unroll
    for (int i = 0; i < PER; i++) {
        vals[i] = p[tid + i * 256];
        lmax = fmaxf(lmax, vals[i]);
    }

    __shared__ float red[8];
    #pragma unroll
    for (int o = 16; o; o >>= 1) lmax = fmaxf(lmax, __shfl_xor_sync(0xFFFFFFFFu, lmax, o));
    if ((tid & 31) == 0) red[tid >> 5] = lmax;
    __syncthreads();
    float m = red[0];
    #pragma unroll
    for (int w = 1; w < 8; w++) m = fmaxf(m, red[w]);
    __syncthreads();

    float lsum = 0.f;
    #pragma unroll
    for (int i = 0; i < PER; i++) {
        vals[i] = expf(vals[i] - m);
        lsum += vals[i];
    }
    #pragma unroll
    for (int o = 16; o; o >>= 1) lsum += __shfl_xor_sync(0xFFFFFFFFu, lsum, o);
    if ((tid & 31) == 0) red[tid >> 5] = lsum;
    __syncthreads();
    float s = 0.f;
    #pragma unroll
    for (int w = 0; w < 8; w++) s += red[w];
    float inv = 1.0f / s;

    #pragma unroll
    for (int i = 0; i < PER; i++) p[tid + i * 256] = vals[i] * inv;
}

extern "C" void kernel_launch(void* const* d_in, const int* in_sizes, int n_in,
                              void* d_out, int out_size)
{
    const float* x  = (const float*)d_in[0];
    const float* wq = (const float*)d_in[1];
    const float* wk = (const float*)d_in[2];
    const float* wv = (const float*)d_in[3];
    float* out = (float*)d_out;

    float *q, *k, *v, *s;
    cudaGetSymbolAddress((void**)&q, g_q);
    cudaGetSymbolAddress((void**)&k, g_k);
    cudaGetSymbolAddress((void**)&v, g_v);
    cudaGetSymbolAddress((void**)&s, g_s);

    dim3 blk(256);

    // 1) Q,K,V projections: [8192,1024] @ [1024,1024]
    dim3 gQKV(D_ / BN, M_TOT / BM, 1);
    sgemm_nn<<<gQKV, blk>>>(x, wq, q, M_TOT, D_, D_, 0, 0, 0);
    sgemm_nn<<<gQKV, blk>>>(x, wk, k, M_TOT, D_, D_, 0, 0, 0);
    sgemm_nn<<<gQKV, blk>>>(x, wv, v, M_TOT, D_, D_, 0, 0, 0);

    // 2) scores[b] = Q[b] @ K[b]^T : [2048,1024] x [2048,1024]^T -> [2048,2048]
    dim3 gS(S_ / BN, S_ / BM, B_);
    sgemm_nt<<<gS, blk>>>(q, k, s, S_, S_, D_,
                          (long)S_ * D_, (long)S_ * D_, (long)S_ * S_);

    // 3) softmax over last dim, in place
    softmax_rows<<<B_ * S_, blk>>>(s, S_);

    // 4) out[b] = weights[b] @ V[b] : [2048,2048] x [2048,1024] -> [2048,1024]
    dim3 gO(D_ / BN, S_ / BM, B_);
    sgemm_nn<<<gO, blk>>>(s, v, out, S_, D_, S_,
                          (long)S_ * S_, (long)S_ * D_, (long)S_ * D_);
}

// round 7
// speedup vs baseline: 1.5785x; 1.5785x over previous
#include <cuda_runtime.h>
#include <cuda_bf16.h>
#include <math.h>
#include <stdint.h>

#define B_  4
#define S_  2048
#define D_  1024
#define M_TOT (B_ * S_)   // 8192

typedef __nv_bfloat16 bf16;

// ---------------- scratch (allocation-free rule: __device__ globals) ----------------
__device__ bf16  g_x0[(size_t)M_TOT * D_], g_x1[(size_t)M_TOT * D_], g_x2[(size_t)M_TOT * D_];
__device__ bf16  g_wq0[(size_t)D_ * D_], g_wq1[(size_t)D_ * D_], g_wq2[(size_t)D_ * D_];
__device__ bf16  g_wk0[(size_t)D_ * D_], g_wk1[(size_t)D_ * D_], g_wk2[(size_t)D_ * D_];
__device__ bf16  g_wv0[(size_t)D_ * D_], g_wv1[(size_t)D_ * D_], g_wv2[(size_t)D_ * D_];
__device__ bf16  g_q0[(size_t)M_TOT * D_], g_q1[(size_t)M_TOT * D_], g_q2[(size_t)M_TOT * D_];
__device__ bf16  g_k0[(size_t)M_TOT * D_], g_k1[(size_t)M_TOT * D_], g_k2[(size_t)M_TOT * D_];
__device__ bf16  g_v0[(size_t)M_TOT * D_], g_v1[(size_t)M_TOT * D_];
__device__ bf16  g_vT0[(size_t)M_TOT * D_], g_vT1[(size_t)M_TOT * D_];   // [B][D,S]
__device__ float g_s[(size_t)B_ * S_ * S_];       // scores fp32
__device__ bf16  g_w0[(size_t)B_ * S_ * S_], g_w1[(size_t)B_ * S_ * S_]; // softmax weights split

// ---------------- helpers ----------------
__device__ __forceinline__ uint32_t smem_u32(const void* p) {
    uint32_t a;
    asm("{ .reg .u64 t; cvta.to.shared.u64 t, %1; cvt.u32.u64 %0, t; }" : "=r"(a) : "l"(p));
    return a;
}
__device__ __forceinline__ void cp_async16(uint32_t dst, const void* src) {
    asm volatile("cp.async.cg.shared.global [%0], [%1], 16;" :: "r"(dst), "l"(src) : "memory");
}
__device__ __forceinline__ void cp_commit() { asm volatile("cp.async.commit_group;" ::: "memory"); }
__device__ __forceinline__ void cp_wait0()  { asm volatile("cp.async.wait_group 0;"  ::: "memory"); }

__device__ __forceinline__ void ldsm_x4(uint32_t* r, uint32_t addr) {
    asm volatile("ldmatrix.sync.aligned.m8n8.x4.shared.b16 {%0,%1,%2,%3}, [%4];"
        : "=r"(r[0]), "=r"(r[1]), "=r"(r[2]), "=r"(r[3]) : "r"(addr));
}
__device__ __forceinline__ void ldsm_x2(uint32_t* r, uint32_t addr) {
    asm volatile("ldmatrix.sync.aligned.m8n8.x2.shared.b16 {%0,%1}, [%2];"
        : "=r"(r[0]), "=r"(r[1]) : "r"(addr));
}
__device__ __forceinline__ void mma16816(float* c, const uint32_t* a, const uint32_t* b) {
    asm volatile(
        "mma.sync.aligned.m16n8k16.row.col.f32.bf16.bf16.f32 "
        "{%0,%1,%2,%3}, {%4,%5,%6,%7}, {%8,%9}, {%0,%1,%2,%3};"
        : "+f"(c[0]), "+f"(c[1]), "+f"(c[2]), "+f"(c[3])
        : "r"(a[0]), "r"(a[1]), "r"(a[2]), "r"(a[3]), "r"(b[0]), "r"(b[1]));
}

// ---------------- GEMM: C[M,N] = A[M,K] * B[N,K]^T with NS-way split operands ----
// terms: all (i,j), i+j <= NS-1  (NS=2: 3 terms; NS=3: 6 terms)
// mode 0: fp32 C ; mode 1: 2-way bf16 (C0,C1) ; mode 2: 3-way bf16 (C0,C1,C2)
#define GBM 128
#define GBN 128
#define GBK 32
#define TILE_BYTES (128 * 40 * 2)     // 128 rows x 80 B pitch = 10240

template<int NS>
__global__ __launch_bounds__(256, 1) void mma_gemm(
    const bf16* __restrict__ A0, const bf16* __restrict__ A1, const bf16* __restrict__ A2,
    const bf16* __restrict__ B0, const bf16* __restrict__ B1, const bf16* __restrict__ B2,
    float* __restrict__ C, bf16* __restrict__ C0, bf16* __restrict__ C1, bf16* __restrict__ C2,
    int M, int N, int K, long sA, long sB, long sC, int mode)
{
    constexpr int STAGE_BYTES = 2 * NS * TILE_BYTES;
    extern __shared__ char sm[];
    const uint32_t sbase = smem_u32(sm);

    const int tid  = threadIdx.x;
    const int wid  = tid >> 5;
    const int lane = tid & 31;
    const int gid  = lane >> 2;
    const int tig  = lane & 3;

    const int by = blockIdx.y * GBM;
    const int bx = blockIdx.x * GBN;

    const bf16* srcs[6];
    srcs[0] = A0 + (long)blockIdx.z * sA + (long)by * K;
    srcs[1] = A1 + (long)blockIdx.z * sA + (long)by * K;
    srcs[2] = (NS == 3) ? A2 + (long)blockIdx.z * sA + (long)by * K : nullptr;
    srcs[NS + 0] = B0 + (long)blockIdx.z * sB + (long)bx * K;
    srcs[NS + 1] = B1 + (long)blockIdx.z * sB + (long)bx * K;
    if (NS == 3) srcs[5] = B2 + (long)blockIdx.z * sB + (long)bx * K;

    const int NT = K / GBK;

    auto load_stage = [&](int st, int kt) {
        #pragma unroll
        for (int t = 0; t < 2 * NS; t++) {
            const char* sp = (const char*)srcs[t] + kt * 64;
            uint32_t db = sbase + st * STAGE_BYTES + t * TILE_BYTES;
            #pragma unroll
            for (int p = 0; p < 2; p++) {
                int idx = p * 256 + tid;       // 0..511
                int row = idx >> 2;
                int c   = idx & 3;
                cp_async16(db + row * 80 + c * 16, sp + (long)row * K * 2 + c * 16);
            }
        }
        cp_commit();
    };

    const int wm = (wid & 1) * 64;
    const int wn = (wid >> 1) * 32;

    float acc[4][4][4] = {};

    load_stage(0, 0);

    for (int kt = 0; kt < NT; kt++) {
        cp_wait0();
        __syncthreads();
        if (kt + 1 < NT) load_stage((kt + 1) & 1, kt + 1);

        uint32_t abase = sbase + (kt & 1) * STAGE_BYTES;
        #pragma unroll
        for (int ks = 0; ks < GBK; ks += 16) {
            uint32_t a[NS][4][4];
            #pragma unroll
            for (int mt = 0; mt < 4; mt++) {
                uint32_t ra = abase + (wm + mt * 16 + (lane & 15)) * 80
                            + (ks + ((lane >> 4) << 3)) * 2;
                #pragma unroll
                for (int s = 0; s < NS; s++)
                    ldsm_x4(a[s][mt], ra + s * TILE_BYTES);
            }
            #pragma unroll
            for (int nt = 0; nt < 4; nt++) {
                uint32_t b[NS][2];
                uint32_t rb = abase + NS * TILE_BYTES + (wn + nt * 8 + (lane & 7)) * 80
                            + (ks + ((lane >> 3) & 1) * 8) * 2;
                #pragma unroll
                for (int s = 0; s < NS; s++)
                    ldsm_x2(b[s], rb + s * TILE_BYTES);
                #pragma unroll
                for (int mt = 0; mt < 4; mt++) {
                    #pragma unroll
                    for (int i = 0; i < NS; i++)
                        #pragma unroll
                        for (int j = 0; j < NS; j++)
                            if (i + j <= NS - 1)
                                mma16816(acc[mt][nt], a[i][mt], b[j]);
                }
            }
        }
        __syncthreads();
    }

    // epilogue
    #pragma unroll
    for (int mt = 0; mt < 4; mt++) {
        #pragma unroll
        for (int nt = 0; nt < 4; nt++) {
            int col = bx + wn + nt * 8 + 2 * tig;
            #pragma unroll
            for (int h = 0; h < 2; h++) {
                int row = by + wm + mt * 16 + gid + h * 8;
                float v0 = acc[mt][nt][2 * h + 0];
                float v1 = acc[mt][nt][2 * h + 1];
                if (mode == 0) {
                    *(float2*)(C + (long)blockIdx.z * sC + (long)row * N + col)
                        = make_float2(v0, v1);
                } else {
                    long base = (long)row * N + col;
                    bf16 h0 = __float2bfloat16(v0);
                    bf16 h1 = __float2bfloat16(v1);
                    float r0 = v0 - __bfloat162float(h0);
                    float r1 = v1 - __bfloat162float(h1);
                    bf16 m0 = __float2bfloat16(r0);
                    bf16 m1 = __float2bfloat16(r1);
                    __nv_bfloat162 hp; hp.x = h0; hp.y = h1;
                    __nv_bfloat162 mp; mp.x = m0; mp.y = m1;
                    *(__nv_bfloat162*)(C0 + base) = hp;
                    *(__nv_bfloat162*)(C1 + base) = mp;
                    if (mode == 2) {
                        bf16 l0 = __float2bfloat16(r0 - __bfloat162float(m0));
                        bf16 l1 = __float2bfloat16(r1 - __bfloat162float(m1));
                        __nv_bfloat162 lp; lp.x = l0; lp.y = l1;
                        *(__nv_bfloat162*)(C2 + base) = lp;
                    }
                }
            }
        }
    }
}

// ---------------- split x: fp32 -> 3-way bf16 ----------------
__global__ __launch_bounds__(256) void split3_f32(const float* __restrict__ in,
        bf16* __restrict__ o0, bf16* __restrict__ o1, bf16* __restrict__ o2, long n)
{
    long i = ((long)blockIdx.x * 256 + threadIdx.x) * 4;
    if (i >= n) return;
    float4 v = *(const float4*)(in + i);
    float vv[4] = {v.x, v.y, v.z, v.w};
    bf16 h[4], m[4], l[4];
    #pragma unroll
    for (int j = 0; j < 4; j++) {
        h[j] = __float2bfloat16(vv[j]);
        float r = vv[j] - __bfloat162float(h[j]);
        m[j] = __float2bfloat16(r);
        l[j] = __float2bfloat16(r - __bfloat162float(m[j]));
    }
    #pragma unroll
    for (int j = 0; j < 4; j++) { o0[i + j] = h[j]; o1[i + j] = m[j]; o2[i + j] = l[j]; }
}

// ---------------- split + transpose w: fp32 [K,N] -> 3-way bf16 [N,K] ----------------
__global__ __launch_bounds__(256) void splitT3_f32(const float* __restrict__ in,
        bf16* __restrict__ o0, bf16* __restrict__ o1, bf16* __restrict__ o2, int Kd, int Nd)
{
    __shared__ float t[32][33];
    int tx = threadIdx.x & 31, ty = threadIdx.x >> 5;   // 32 x 8
    int c0 = blockIdx.x * 32, r0 = blockIdx.y * 32;
    #pragma unroll
    for (int j = 0; j < 4; j++)
        t[ty + j * 8][tx] = in[(long)(r0 + ty + j * 8) * Nd + c0 + tx];
    __syncthreads();
    #pragma unroll
    for (int j = 0; j < 4; j++) {
        float v = t[tx][ty + j * 8];
        bf16 h = __float2bfloat16(v);
        float r = v - __bfloat162float(h);
        bf16 m = __float2bfloat16(r);
        bf16 l = __float2bfloat16(r - __bfloat162float(m));
        long o = (long)(c0 + ty + j * 8) * Kd + r0 + tx;
        o0[o] = h; o1[o] = m; o2[o] = l;
    }
}

// ---------------- batched bf16 transpose: [B][S,D] -> [B][D,S]  (z = batch*2 + which) ----------------
__global__ __launch_bounds__(256) void transpose_bf16(const bf16* __restrict__ inh, const bf16* __restrict__ inl,
                                                      bf16* __restrict__ outh, bf16* __restrict__ outl)
{
    __shared__ bf16 t[32][33];
    int which = blockIdx.z & 1, b = blockIdx.z >> 1;
    const bf16* in = which ? inl : inh;
    bf16* out = which ? outl : outh;
    in  += (long)b * S_ * D_;
    out += (long)b * S_ * D_;
    int tx = threadIdx.x & 31, ty = threadIdx.x >> 5;
    int c0 = blockIdx.x * 32, r0 = blockIdx.y * 32;
    #pragma unroll
    for (int j = 0; j < 4; j++)
        t[ty + j * 8][tx] = in[(long)(r0 + ty + j * 8) * D_ + c0 + tx];
    __syncthreads();
    #pragma unroll
    for (int j = 0; j < 4; j++)
        out[(long)(c0 + ty + j * 8) * S_ + r0 + tx] = t[tx][ty + j * 8];
}

// ---------------- softmax: fp32 scores row -> 2-way bf16 weights ----------------
__global__ __launch_bounds__(256) void softmax_rows(const float* __restrict__ Sp,
                                                    bf16* __restrict__ W0, bf16* __restrict__ W1)
{
    const float* p = Sp + (long)blockIdx.x * S_;
    bf16* p0 = W0 + (long)blockIdx.x * S_;
    bf16* p1 = W1 + (long)blockIdx.x * S_;
    const int tid = threadIdx.x;
    const int PER = S_ / 256;

    float vals[PER];
    float lmax = -INFINITY;
    #pragma unroll
    for (int i = 0; i < PER; i++) {
        vals[i] = p[tid + i * 256];
        lmax = fmaxf(lmax, vals[i]);
    }
    __shared__ float red[8];
    #pragma unroll
    for (int o = 16; o; o >>= 1) lmax = fmaxf(lmax, __shfl_xor_sync(0xFFFFFFFFu, lmax, o));
    if ((tid & 31) == 0) red[tid >> 5] = lmax;
    __syncthreads();
    float m = red[0];
    #pragma unroll
    for (int w = 1; w < 8; w++) m = fmaxf(m, red[w]);
    __syncthreads();

    float lsum = 0.f;
    #pragma unroll
    for (int i = 0; i < PER; i++) { vals[i] = expf(vals[i] - m); lsum += vals[i]; }
    #pragma unroll
    for (int o = 16; o; o >>= 1) lsum += __shfl_xor_sync(0xFFFFFFFFu, lsum, o);
    if ((tid & 31) == 0) red[tid >> 5] = lsum;
    __syncthreads();
    float s = 0.f;
    #pragma unroll
    for (int w = 0; w < 8; w++) s += red[w];
    float inv = 1.0f / s;
    #pragma unroll
    for (int i = 0; i < PER; i++) {
        float w = vals[i] * inv;
        bf16 h = __float2bfloat16(w);
        bf16 l = __float2bfloat16(w - __bfloat162float(h));
        p0[tid + i * 256] = h;
        p1[tid + i * 256] = l;
    }
}

// ---------------- launch ----------------
extern "C" void kernel_launch(void* const* d_in, const int* in_sizes, int n_in,
                              void* d_out, int out_size)
{
    const float* x  = (const float*)d_in[0];
    const float* wq = (const float*)d_in[1];
    const float* wk = (const float*)d_in[2];
    const float* wv = (const float*)d_in[3];
    float* out = (float*)d_out;

    static bool attr_done = false;
    if (!attr_done) {
        cudaFuncSetAttribute(mma_gemm<2>, cudaFuncAttributeMaxDynamicSharedMemorySize, 2 * 4 * TILE_BYTES);
        cudaFuncSetAttribute(mma_gemm<3>, cudaFuncAttributeMaxDynamicSharedMemorySize, 2 * 6 * TILE_BYTES);
        attr_done = true;
    }

    bf16 *x0, *x1, *x2, *wq0, *wq1, *wq2, *wk0, *wk1, *wk2, *wv0, *wv1, *wv2;
    bf16 *q0, *q1, *q2, *k0, *k1, *k2, *v0, *v1, *vT0, *vT1, *w0, *w1;
    float* sc;
    cudaGetSymbolAddress((void**)&x0, g_x0);   cudaGetSymbolAddress((void**)&x1, g_x1);
    cudaGetSymbolAddress((void**)&x2, g_x2);
    cudaGetSymbolAddress((void**)&wq0, g_wq0); cudaGetSymbolAddress((void**)&wq1, g_wq1);
    cudaGetSymbolAddress((void**)&wq2, g_wq2);
    cudaGetSymbolAddress((void**)&wk0, g_wk0); cudaGetSymbolAddress((void**)&wk1, g_wk1);
    cudaGetSymbolAddress((void**)&wk2, g_wk2);
    cudaGetSymbolAddress((void**)&wv0, g_wv0); cudaGetSymbolAddress((void**)&wv1, g_wv1);
    cudaGetSymbolAddress((void**)&wv2, g_wv2);
    cudaGetSymbolAddress((void**)&q0, g_q0);   cudaGetSymbolAddress((void**)&q1, g_q1);
    cudaGetSymbolAddress((void**)&q2, g_q2);
    cudaGetSymbolAddress((void**)&k0, g_k0);   cudaGetSymbolAddress((void**)&k1, g_k1);
    cudaGetSymbolAddress((void**)&k2, g_k2);
    cudaGetSymbolAddress((void**)&v0, g_v0);   cudaGetSymbolAddress((void**)&v1, g_v1);
    cudaGetSymbolAddress((void**)&vT0, g_vT0); cudaGetSymbolAddress((void**)&vT1, g_vT1);
    cudaGetSymbolAddress((void**)&sc, g_s);
    cudaGetSymbolAddress((void**)&w0, g_w0);   cudaGetSymbolAddress((void**)&w1, g_w1);

    const int SM2 = 2 * 4 * TILE_BYTES;
    const int SM3 = 2 * 6 * TILE_BYTES;

    // 1) splits
    split3_f32<<<(M_TOT * (long)D_) / (256 * 4), 256>>>(x, x0, x1, x2, (long)M_TOT * D_);
    dim3 tgrid(D_ / 32, D_ / 32);
    splitT3_f32<<<tgrid, 256>>>(wq, wq0, wq1, wq2, D_, D_);
    splitT3_f32<<<tgrid, 256>>>(wk, wk0, wk1, wk2, D_, D_);
    splitT3_f32<<<tgrid, 256>>>(wv, wv0, wv1, wv2, D_, D_);

    // 2) projections: q,k high precision (NS=3, 6 terms) -> 3-way split; v NS=2 -> 2-way
    dim3 gP(D_ / GBN, M_TOT / GBM, 1);
    mma_gemm<3><<<gP, 256, SM3>>>(x0, x1, x2, wq0, wq1, wq2,
                                  nullptr, q0, q1, q2, M_TOT, D_, D_, 0, 0, 0, 2);
    mma_gemm<3><<<gP, 256, SM3>>>(x0, x1, x2, wk0, wk1, wk2,
                                  nullptr, k0, k1, k2, M_TOT, D_, D_, 0, 0, 0, 2);
    mma_gemm<2><<<gP, 256, SM2>>>(x0, x1, nullptr, wv0, wv1, nullptr,
                                  nullptr, v0, v1, nullptr, M_TOT, D_, D_, 0, 0, 0, 1);

    // 3) transpose V halves: [B][S,D] -> [B][D,S]
    dim3 gT(D_ / 32, S_ / 32, B_ * 2);
    transpose_bf16<<<gT, 256>>>(v0, v1, vT0, vT1);

    // 4) scores[b] = Q[b] * K[b]^T (NS=3, 6 terms) -> fp32
    dim3 gS(S_ / GBN, S_ / GBM, B_);
    mma_gemm<3><<<gS, 256, SM3>>>(q0, q1, q2, k0, k1, k2,
                                  sc, nullptr, nullptr, nullptr,
                                  S_, S_, D_, (long)S_ * D_, (long)S_ * D_, (long)S_ * S_, 0);

    // 5) softmax -> 2-way bf16 weights
    softmax_rows<<<B_ * S_, 256>>>(sc, w0, w1);

    // 6) out[b] = W[b] * V[b] (NS=2) -> fp32
    dim3 gO(D_ / GBN, S_ / GBM, B_);
    mma_gemm<2><<<gO, 256, SM2>>>(w0, w1, nullptr, vT0, vT1, nullptr,
                                  out, nullptr, nullptr, nullptr,
                                  S_, D_, S_, (long)S_ * S_, (long)D_ * S_, (long)S_ * D_, 0);
}

// round 8
// speedup vs baseline: 2.1056x; 1.3339x over previous
#include <cuda_runtime.h>
#include <cuda_bf16.h>
#include <math.h>
#include <stdint.h>

#define B_  4
#define S_  2048
#define D_  1024
#define M_TOT (B_ * S_)   // 8192

typedef __nv_bfloat16 bf16;

// ---------------- scratch (allocation-free rule: __device__ globals) ----------------
__device__ bf16  g_x0[(size_t)M_TOT * D_], g_x1[(size_t)M_TOT * D_], g_x2[(size_t)M_TOT * D_];
__device__ bf16  g_wq0[(size_t)D_ * D_], g_wq1[(size_t)D_ * D_], g_wq2[(size_t)D_ * D_];
__device__ bf16  g_wk0[(size_t)D_ * D_], g_wk1[(size_t)D_ * D_], g_wk2[(size_t)D_ * D_];
__device__ bf16  g_wv0[(size_t)D_ * D_], g_wv1[(size_t)D_ * D_], g_wv2[(size_t)D_ * D_];
__device__ bf16  g_q0[(size_t)M_TOT * D_], g_q1[(size_t)M_TOT * D_], g_q2[(size_t)M_TOT * D_];
__device__ bf16  g_k0[(size_t)M_TOT * D_], g_k1[(size_t)M_TOT * D_], g_k2[(size_t)M_TOT * D_];
__device__ bf16  g_v0[(size_t)M_TOT * D_], g_v1[(size_t)M_TOT * D_];
__device__ bf16  g_vT0[(size_t)M_TOT * D_], g_vT1[(size_t)M_TOT * D_];   // [B][D,S]
__device__ float g_s[(size_t)B_ * S_ * S_];       // scores fp32
__device__ bf16  g_w0[(size_t)B_ * S_ * S_], g_w1[(size_t)B_ * S_ * S_]; // softmax weights split

// ---------------- helpers ----------------
__device__ __forceinline__ uint32_t smem_u32(const void* p) {
    uint32_t a;
    asm("{ .reg .u64 t; cvta.to.shared.u64 t, %1; cvt.u32.u64 %0, t; }" : "=r"(a) : "l"(p));
    return a;
}
__device__ __forceinline__ void cp_async16(uint32_t dst, const void* src) {
    asm volatile("cp.async.cg.shared.global [%0], [%1], 16;" :: "r"(dst), "l"(src) : "memory");
}
__device__ __forceinline__ void cp_commit() { asm volatile("cp.async.commit_group;" ::: "memory"); }
__device__ __forceinline__ void cp_wait0()  { asm volatile("cp.async.wait_group 0;"  ::: "memory"); }

__device__ __forceinline__ void ldsm_x4(uint32_t* r, uint32_t addr) {
    asm volatile("ldmatrix.sync.aligned.m8n8.x4.shared.b16 {%0,%1,%2,%3}, [%4];"
        : "=r"(r[0]), "=r"(r[1]), "=r"(r[2]), "=r"(r[3]) : "r"(addr));
}
__device__ __forceinline__ void ldsm_x2(uint32_t* r, uint32_t addr) {
    asm volatile("ldmatrix.sync.aligned.m8n8.x2.shared.b16 {%0,%1}, [%2];"
        : "=r"(r[0]), "=r"(r[1]) : "r"(addr));
}
__device__ __forceinline__ void mma16816(float* c, const uint32_t* a, const uint32_t* b) {
    asm volatile(
        "mma.sync.aligned.m16n8k16.row.col.f32.bf16.bf16.f32 "
        "{%0,%1,%2,%3}, {%4,%5,%6,%7}, {%8,%9}, {%0,%1,%2,%3};"
        : "+f"(c[0]), "+f"(c[1]), "+f"(c[2]), "+f"(c[3])
        : "r"(a[0]), "r"(a[1]), "r"(a[2]), "r"(a[3]), "r"(b[0]), "r"(b[1]));
}

// Swizzled tile layout: 128 logical rows x 64 B (32 bf16, one GBK=32 K-slice).
// Rows packed pairwise into 64 storage rows of 128 B: (row&63)*128 + (row>>6)*64,
// then SW128 XOR. ldmatrix 8-row groups stay within one half -> conflict-free.
#define SWZ128(x) ((x) ^ (((x) >> 3) & 0x70))
__device__ __forceinline__ uint32_t tile_off(uint32_t row, uint32_t colb) {
    return SWZ128(((row & 63u) << 7) + ((row >> 6) << 6) + colb);
}

// ---------------- GEMM: C[M,N] = A[M,K] * B[N,K]^T with NS-way split operands ----
// terms: all (i,j), i+j <= NS-1  (NS=2: 3 terms; NS=3: 6 terms)
// mode 0: fp32 C ; mode 1: 2-way bf16 (C0,C1) ; mode 2: 3-way bf16 (C0,C1,C2)
// zmode 0: blockIdx.z = batch (strides sA/sB/sC)
// zmode 1: blockIdx.z selects operand/output set (0: B*/C*, 1: Bb*/Cb*)  [QK fusion]
#define GBM 128
#define GBN 128
#define GBK 32
#define TILE_BYTES 8192

template<int NS>
__global__ __launch_bounds__(256, 2) void mma_gemm(
    const bf16* __restrict__ A0, const bf16* __restrict__ A1, const bf16* __restrict__ A2,
    const bf16* B0, const bf16* B1, const bf16* B2,
    const bf16* B0b, const bf16* B1b, const bf16* B2b,
    float* C, bf16* C0, bf16* C1, bf16* C2,
    float* Cb, bf16* C0b, bf16* C1b, bf16* C2b,
    int M, int N, int K, long sA, long sB, long sC, int mode, int zmode)
{
    constexpr int STAGE_BYTES = 2 * NS * TILE_BYTES;
    extern __shared__ char sm[];
    const uint32_t sbase = smem_u32(sm);

    const int tid  = threadIdx.x;
    const int wid  = tid >> 5;
    const int lane = tid & 31;
    const int gid  = lane >> 2;
    const int tig  = lane & 3;

    if (zmode == 1 && blockIdx.z == 1) {
        B0 = B0b; B1 = B1b; B2 = B2b;
        C = Cb; C0 = C0b; C1 = C1b; C2 = C2b;
    }
    const long zb = (zmode == 0) ? (long)blockIdx.z : 0;

    const int by = blockIdx.y * GBM;
    const int bx = blockIdx.x * GBN;

    const bf16* srcs[2 * NS];
    srcs[0] = A0 + zb * sA + (long)by * K;
    srcs[1] = A1 + zb * sA + (long)by * K;
    if (NS == 3) srcs[2] = A2 + zb * sA + (long)by * K;
    srcs[NS + 0] = B0 + zb * sB + (long)bx * K;
    srcs[NS + 1] = B1 + zb * sB + (long)bx * K;
    if (NS == 3) srcs[NS + 2] = B2 + zb * sB + (long)bx * K;

    const int NT = K / GBK;

    auto load_stage = [&](int st, int kt) {
        #pragma unroll
        for (int t = 0; t < 2 * NS; t++) {
            const char* sp = (const char*)srcs[t] + kt * 64;
            uint32_t db = sbase + st * STAGE_BYTES + t * TILE_BYTES;
            #pragma unroll
            for (int p = 0; p < 2; p++) {
                int idx = p * 256 + tid;       // 0..511
                uint32_t row = idx >> 2;
                uint32_t c   = idx & 3;
                cp_async16(db + tile_off(row, c << 4), sp + (long)row * K * 2 + c * 16);
            }
        }
        cp_commit();
    };

    const int wm = (wid & 1) * 64;
    const int wn = (wid >> 1) * 32;

    float acc[4][4][4] = {};

    load_stage(0, 0);

    for (int kt = 0; kt < NT; kt++) {
        cp_wait0();
        __syncthreads();
        if (kt + 1 < NT) load_stage((kt + 1) & 1, kt + 1);

        uint32_t abase = sbase + (kt & 1) * STAGE_BYTES;
        #pragma unroll
        for (int ks = 0; ks < GBK; ks += 16) {
            // B fragments upfront (NS*4 ldsm_x2 = 8 or 12)
            uint32_t b[NS][4][2];
            #pragma unroll
            for (int nt = 0; nt < 4; nt++) {
                uint32_t r = wn + nt * 8 + (lane & 7);
                uint32_t cb = ((ks >> 3) + ((lane >> 3) & 1)) << 4;
                uint32_t rb = abase + NS * TILE_BYTES + tile_off(r, cb);
                #pragma unroll
                for (int s = 0; s < NS; s++)
                    ldsm_x2(b[s][nt], rb + s * TILE_BYTES);
            }
            // A per mt, then MMAs (keeps A-frag live range short)
            #pragma unroll
            for (int mt = 0; mt < 4; mt++) {
                uint32_t a[NS][4];
                uint32_t r = wm + mt * 16 + (lane & 15);
                uint32_t cb = ((ks >> 3) + (lane >> 4)) << 4;
                uint32_t ra = abase + tile_off(r, cb);
                #pragma unroll
                for (int s = 0; s < NS; s++)
                    ldsm_x4(a[s], ra + s * TILE_BYTES);
                #pragma unroll
                for (int nt = 0; nt < 4; nt++) {
                    #pragma unroll
                    for (int i = 0; i < NS; i++)
                        #pragma unroll
                        for (int j = 0; j < NS; j++)
                            if (i + j <= NS - 1)
                                mma16816(acc[mt][nt], a[i], b[j][nt]);
                }
            }
        }
        __syncthreads();
    }

    // epilogue
    #pragma unroll
    for (int mt = 0; mt < 4; mt++) {
        #pragma unroll
        for (int nt = 0; nt < 4; nt++) {
            int col = bx + wn + nt * 8 + 2 * tig;
            #pragma unroll
            for (int h = 0; h < 2; h++) {
                int row = by + wm + mt * 16 + gid + h * 8;
                float v0 = acc[mt][nt][2 * h + 0];
                float v1 = acc[mt][nt][2 * h + 1];
                if (mode == 0) {
                    *(float2*)(C + zb * sC + (long)row * N + col) = make_float2(v0, v1);
                } else {
                    long base = (long)row * N + col;
                    bf16 h0 = __float2bfloat16(v0);
                    bf16 h1 = __float2bfloat16(v1);
                    float r0 = v0 - __bfloat162float(h0);
                    float r1 = v1 - __bfloat162float(h1);
                    bf16 m0 = __float2bfloat16(r0);
                    bf16 m1 = __float2bfloat16(r1);
                    __nv_bfloat162 hp; hp.x = h0; hp.y = h1;
                    __nv_bfloat162 mp; mp.x = m0; mp.y = m1;
                    *(__nv_bfloat162*)(C0 + base) = hp;
                    *(__nv_bfloat162*)(C1 + base) = mp;
                    if (mode == 2) {
                        bf16 l0 = __float2bfloat16(r0 - __bfloat162float(m0));
                        bf16 l1 = __float2bfloat16(r1 - __bfloat162float(m1));
                        __nv_bfloat162 lp; lp.x = l0; lp.y = l1;
                        *(__nv_bfloat162*)(C2 + base) = lp;
                    }
                }
            }
        }
    }
}

// ---------------- split x: fp32 -> 3-way bf16 ----------------
__global__ __launch_bounds__(256) void split3_f32(const float* __restrict__ in,
        bf16* __restrict__ o0, bf16* __restrict__ o1, bf16* __restrict__ o2, long n)
{
    long i = ((long)blockIdx.x * 256 + threadIdx.x) * 4;
    if (i >= n) return;
    float4 v = *(const float4*)(in + i);
    float vv[4] = {v.x, v.y, v.z, v.w};
    bf16 h[4], m[4], l[4];
    #pragma unroll
    for (int j = 0; j < 4; j++) {
        h[j] = __float2bfloat16(vv[j]);
        float r = vv[j] - __bfloat162float(h[j]);
        m[j] = __float2bfloat16(r);
        l[j] = __float2bfloat16(r - __bfloat162float(m[j]));
    }
    #pragma unroll
    for (int j = 0; j < 4; j++) { o0[i + j] = h[j]; o1[i + j] = m[j]; o2[i + j] = l[j]; }
}

// ---------------- split + transpose w: fp32 [K,N] -> 3-way bf16 [N,K] ----------------
__global__ __launch_bounds__(256) void splitT3_f32(const float* __restrict__ in,
        bf16* __restrict__ o0, bf16* __restrict__ o1, bf16* __restrict__ o2, int Kd, int Nd)
{
    __shared__ float t[32][33];
    int tx = threadIdx.x & 31, ty = threadIdx.x >> 5;   // 32 x 8
    int c0 = blockIdx.x * 32, r0 = blockIdx.y * 32;
    #pragma unroll
    for (int j = 0; j < 4; j++)
        t[ty + j * 8][tx] = in[(long)(r0 + ty + j * 8) * Nd + c0 + tx];
    __syncthreads();
    #pragma unroll
    for (int j = 0; j < 4; j++) {
        float v = t[tx][ty + j * 8];
        bf16 h = __float2bfloat16(v);
        float r = v - __bfloat162float(h);
        bf16 m = __float2bfloat16(r);
        bf16 l = __float2bfloat16(r - __bfloat162float(m));
        long o = (long)(c0 + ty + j * 8) * Kd + r0 + tx;
        o0[o] = h; o1[o] = m; o2[o] = l;
    }
}

// ---------------- batched bf16 transpose: [B][S,D] -> [B][D,S]  (z = batch*2 + which) ----------------
__global__ __launch_bounds__(256) void transpose_bf16(const bf16* __restrict__ inh, const bf16* __restrict__ inl,
                                                      bf16* __restrict__ outh, bf16* __restrict__ outl)
{
    __shared__ bf16 t[32][33];
    int which = blockIdx.z & 1, b = blockIdx.z >> 1;
    const bf16* in = which ? inl : inh;
    bf16* out = which ? outl : outh;
    in  += (long)b * S_ * D_;
    out += (long)b * S_ * D_;
    int tx = threadIdx.x & 31, ty = threadIdx.x >> 5;
    int c0 = blockIdx.x * 32, r0 = blockIdx.y * 32;
    #pragma unroll
    for (int j = 0; j < 4; j++)
        t[ty + j * 8][tx] = in[(long)(r0 + ty + j * 8) * D_ + c0 + tx];
    __syncthreads();
    #pragma unroll
    for (int j = 0; j < 4; j++)
        out[(long)(c0 + ty + j * 8) * S_ + r0 + tx] = t[tx][ty + j * 8];
}

// ---------------- softmax: fp32 scores row -> 2-way bf16 weights ----------------
__global__ __launch_bounds__(256) void softmax_rows(const float* __restrict__ Sp,
                                                    bf16* __restrict__ W0, bf16* __restrict__ W1)
{
    const float* p = Sp + (long)blockIdx.x * S_;
    bf16* p0 = W0 + (long)blockIdx.x * S_;
    bf16* p1 = W1 + (long)blockIdx.x * S_;
    const int tid = threadIdx.x;
    const int PER = S_ / 256;

    float vals[PER];
    float lmax = -INFINITY;
    #pragma unroll
    for (int i = 0; i < PER; i++) {
        vals[i] = p[tid + i * 256];
        lmax = fmaxf(lmax, vals[i]);
    }
    __shared__ float red[8];
    #pragma unroll
    for (int o = 16; o; o >>= 1) lmax = fmaxf(lmax, __shfl_xor_sync(0xFFFFFFFFu, lmax, o));
    if ((tid & 31) == 0) red[tid >> 5] = lmax;
    __syncthreads();
    float m = red[0];
    #pragma unroll
    for (int w = 1; w < 8; w++) m = fmaxf(m, red[w]);
    __syncthreads();

    float lsum = 0.f;
    #pragma unroll
    for (int i = 0; i < PER; i++) { vals[i] = expf(vals[i] - m); lsum += vals[i]; }
    #pragma unroll
    for (int o = 16; o; o >>= 1) lsum += __shfl_xor_sync(0xFFFFFFFFu, lsum, o);
    if ((tid & 31) == 0) red[tid >> 5] = lsum;
    __syncthreads();
    float s = 0.f;
    #pragma unroll
    for (int w = 0; w < 8; w++) s += red[w];
    float inv = 1.0f / s;
    #pragma unroll
    for (int i = 0; i < PER; i++) {
        float w = vals[i] * inv;
        bf16 h = __float2bfloat16(w);
        bf16 l = __float2bfloat16(w - __bfloat162float(h));
        p0[tid + i * 256] = h;
        p1[tid + i * 256] = l;
    }
}

// ---------------- launch ----------------
extern "C" void kernel_launch(void* const* d_in, const int* in_sizes, int n_in,
                              void* d_out, int out_size)
{
    const float* x  = (const float*)d_in[0];
    const float* wq = (const float*)d_in[1];
    const float* wk = (const float*)d_in[2];
    const float* wv = (const float*)d_in[3];
    float* out = (float*)d_out;

    const int SM2 = 2 * 4 * TILE_BYTES;   // 64 KB
    const int SM3 = 2 * 6 * TILE_BYTES;   // 96 KB

    static bool attr_done = false;
    if (!attr_done) {
        cudaFuncSetAttribute(mma_gemm<2>, cudaFuncAttributeMaxDynamicSharedMemorySize, SM2);
        cudaFuncSetAttribute(mma_gemm<3>, cudaFuncAttributeMaxDynamicSharedMemorySize, SM3);
        attr_done = true;
    }

    bf16 *x0, *x1, *x2, *wq0, *wq1, *wq2, *wk0, *wk1, *wk2, *wv0, *wv1, *wv2;
    bf16 *q0, *q1, *q2, *k0, *k1, *k2, *v0, *v1, *vT0, *vT1, *w0, *w1;
    float* sc;
    cudaGetSymbolAddress((void**)&x0, g_x0);   cudaGetSymbolAddress((void**)&x1, g_x1);
    cudaGetSymbolAddress((void**)&x2, g_x2);
    cudaGetSymbolAddress((void**)&wq0, g_wq0); cudaGetSymbolAddress((void**)&wq1, g_wq1);
    cudaGetSymbolAddress((void**)&wq2, g_wq2);
    cudaGetSymbolAddress((void**)&wk0, g_wk0); cudaGetSymbolAddress((void**)&wk1, g_wk1);
    cudaGetSymbolAddress((void**)&wk2, g_wk2);
    cudaGetSymbolAddress((void**)&wv0, g_wv0); cudaGetSymbolAddress((void**)&wv1, g_wv1);
    cudaGetSymbolAddress((void**)&wv2, g_wv2);
    cudaGetSymbolAddress((void**)&q0, g_q0);   cudaGetSymbolAddress((void**)&q1, g_q1);
    cudaGetSymbolAddress((void**)&q2, g_q2);
    cudaGetSymbolAddress((void**)&k0, g_k0);   cudaGetSymbolAddress((void**)&k1, g_k1);
    cudaGetSymbolAddress((void**)&k2, g_k2);
    cudaGetSymbolAddress((void**)&v0, g_v0);   cudaGetSymbolAddress((void**)&v1, g_v1);
    cudaGetSymbolAddress((void**)&vT0, g_vT0); cudaGetSymbolAddress((void**)&vT1, g_vT1);
    cudaGetSymbolAddress((void**)&sc, g_s);
    cudaGetSymbolAddress((void**)&w0, g_w0);   cudaGetSymbolAddress((void**)&w1, g_w1);

    // 1) splits
    split3_f32<<<(M_TOT * (long)D_) / (256 * 4), 256>>>(x, x0, x1, x2, (long)M_TOT * D_);
    dim3 tgrid(D_ / 32, D_ / 32);
    splitT3_f32<<<tgrid, 256>>>(wq, wq0, wq1, wq2, D_, D_);
    splitT3_f32<<<tgrid, 256>>>(wk, wk0, wk1, wk2, D_, D_);
    splitT3_f32<<<tgrid, 256>>>(wv, wv0, wv1, wv2, D_, D_);

    // 2) fused Q+K projections (NS=3, 6 terms, z selects weight/output set)
    dim3 gQK(D_ / GBN, M_TOT / GBM, 2);
    mma_gemm<3><<<gQK, 256, SM3>>>(x0, x1, x2,
                                   wq0, wq1, wq2, wk0, wk1, wk2,
                                   nullptr, q0, q1, q2,
                                   nullptr, k0, k1, k2,
                                   M_TOT, D_, D_, 0, 0, 0, 2, 1);
    // V projection (NS=2, 3 terms)
    dim3 gP(D_ / GBN, M_TOT / GBM, 1);
    mma_gemm<2><<<gP, 256, SM2>>>(x0, x1, nullptr,
                                  wv0, wv1, nullptr, nullptr, nullptr, nullptr,
                                  nullptr, v0, v1, nullptr,
                                  nullptr, nullptr, nullptr, nullptr,
                                  M_TOT, D_, D_, 0, 0, 0, 1, 0);

    // 3) transpose V halves: [B][S,D] -> [B][D,S]
    dim3 gT(D_ / 32, S_ / 32, B_ * 2);
    transpose_bf16<<<gT, 256>>>(v0, v1, vT0, vT1);

    // 4) scores[b] = Q[b] * K[b]^T (NS=3, 6 terms) -> fp32
    dim3 gS(S_ / GBN, S_ / GBM, B_);
    mma_gemm<3><<<gS, 256, SM3>>>(q0, q1, q2,
                                  k0, k1, k2, nullptr, nullptr, nullptr,
                                  sc, nullptr, nullptr, nullptr,
                                  nullptr, nullptr, nullptr, nullptr,
                                  S_, S_, D_, (long)S_ * D_, (long)S_ * D_, (long)S_ * S_, 0, 0);

    // 5) softmax -> 2-way bf16 weights
    softmax_rows<<<B_ * S_, 256>>>(sc, w0, w1);

    // 6) out[b] = W[b] * V[b] (NS=2) -> fp32
    dim3 gO(D_ / GBN, S_ / GBM, B_);
    mma_gemm<2><<<gO, 256, SM2>>>(w0, w1, nullptr,
                                  vT0, vT1, nullptr, nullptr, nullptr, nullptr,
                                  out, nullptr, nullptr, nullptr,
                                  nullptr, nullptr, nullptr, nullptr,
                                  S_, D_, S_, (long)S_ * S_, (long)D_ * S_, (long)S_ * D_, 0, 0);
}